// round 5
// baseline (speedup 1.0000x reference)
#include <cuda_runtime.h>
#include <cstdint>

#define B_ 64
#define T_ 128
#define E_ 256
#define H_ 256          // HH
#define M_ (B_ * T_)    // 8192

// Scratch for x_proj of the current level (reused between levels)
__device__ float g_xp[M_ * H_];

// ---------------- helpers ----------------

__device__ __forceinline__ void fma2(unsigned long long &d,
                                     unsigned long long a,
                                     unsigned long long b) {
    asm("fma.rn.f32x2 %0, %1, %2, %0;" : "+l"(d) : "l"(a), "l"(b));
}

__device__ __forceinline__ unsigned long long pack2(float a, float b) {
    unsigned long long r;
    asm("mov.b64 %0, {%1, %2};" : "=l"(r) : "f"(a), "f"(b));
    return r;
}

__device__ __forceinline__ float lo32(unsigned long long v) {
    return __uint_as_float((unsigned)(v & 0xffffffffull));
}
__device__ __forceinline__ float hi32(unsigned long long v) {
    return __uint_as_float((unsigned)(v >> 32));
}

__device__ __forceinline__ float fast_tanh(float x) {
    float e = __expf(2.0f * x);
    return 1.0f - __fdividef(2.0f, e + 1.0f);
}

__device__ __forceinline__ unsigned smem_u32(const void* p) {
    unsigned a;
    asm("{ .reg .u64 t; cvta.to.shared.u64 t, %1; cvt.u32.u64 %0, t; }"
        : "=r"(a) : "l"(p));
    return a;
}

__device__ __forceinline__ unsigned mapa_rank(unsigned laddr, unsigned rank) {
    unsigned r;
    asm("mapa.shared::cluster.u32 %0, %1, %2;" : "=r"(r) : "r"(laddr), "r"(rank));
    return r;
}

__device__ __forceinline__ void mbar_init(unsigned addr, unsigned cnt) {
    asm volatile("mbarrier.init.shared.b64 [%0], %1;" :: "r"(addr), "r"(cnt) : "memory");
}

__device__ __forceinline__ void mbar_inval(unsigned addr) {
    asm volatile("mbarrier.inval.shared.b64 [%0];" :: "r"(addr) : "memory");
}

__device__ __forceinline__ void mbar_expect_tx(unsigned addr, unsigned bytes) {
    asm volatile("mbarrier.arrive.expect_tx.shared.b64 _, [%0], %1;"
                 :: "r"(addr), "r"(bytes) : "memory");
}

__device__ __forceinline__ void st_async_f32(unsigned daddr, float v, unsigned mbar) {
    asm volatile(
        "st.async.shared::cluster.mbarrier::complete_tx::bytes.f32 [%0], %1, [%2];"
        :: "r"(daddr), "f"(v), "r"(mbar) : "memory");
}

__device__ __forceinline__ void mbar_wait_parity(unsigned addr, unsigned parity) {
    unsigned done;
    asm volatile(
        "{\n\t.reg .pred p;\n\t"
        "mbarrier.try_wait.parity.acquire.cta.shared::cta.b64 p, [%1], %2;\n\t"
        "selp.b32 %0, 1, 0, p;\n\t}"
        : "=r"(done) : "r"(addr), "r"(parity) : "memory");
    if (!done) {
        asm volatile(
            "{\n\t.reg .pred P1;\n\t"
            "WL_%=:\n\t"
            "mbarrier.try_wait.parity.acquire.cta.shared::cta.b64 P1, [%0], %1, 0x989680;\n\t"
            "@P1 bra.uni WD_%=;\n\t"
            "bra.uni WL_%=;\n\t"
            "WD_%=:\n\t}"
            :: "r"(addr), "r"(parity) : "memory");
    }
}

// ---------------- x_proj GEMM ----------------
__global__ __launch_bounds__(256) void xp_gemm(
    const float* __restrict__ Asrc, long lda, const int* __restrict__ tokens,
    const float* __restrict__ Bw, const float* __restrict__ bias)
{
    __shared__ float As[8][128];
    __shared__ float Bs[8][128];

    const int m0 = blockIdx.x * 128;
    const int n0 = blockIdx.y * 128;
    const int tid = threadIdx.x;
    const int tx = tid & 15;
    const int ty = tid >> 4;
    const int lrow = tid >> 1;
    const int lc4 = (tid & 1) * 4;

    unsigned long long acc[8][4];
#pragma unroll
    for (int i = 0; i < 8; i++)
#pragma unroll
        for (int j = 0; j < 4; j++) acc[i][j] = 0ull;

    const float* aptr;
    {
        long ar = m0 + lrow;
        if (tokens) aptr = Asrc + (long)__ldg(tokens + ar) * lda;
        else        aptr = Asrc + ar * lda;
    }
    const float* bptr = Bw + (long)(n0 + lrow) * 256;

    for (int c = 0; c < 256; c += 8) {
        float4 av = *reinterpret_cast<const float4*>(aptr + c + lc4);
        float4 bv = *reinterpret_cast<const float4*>(bptr + c + lc4);
        __syncthreads();
        As[lc4 + 0][lrow] = av.x; As[lc4 + 1][lrow] = av.y;
        As[lc4 + 2][lrow] = av.z; As[lc4 + 3][lrow] = av.w;
        Bs[lc4 + 0][lrow] = bv.x; Bs[lc4 + 1][lrow] = bv.y;
        Bs[lc4 + 2][lrow] = bv.z; Bs[lc4 + 3][lrow] = bv.w;
        __syncthreads();
#pragma unroll
        for (int k = 0; k < 8; k++) {
            float a[8];
            *reinterpret_cast<float4*>(&a[0]) =
                *reinterpret_cast<const float4*>(&As[k][ty * 8]);
            *reinterpret_cast<float4*>(&a[4]) =
                *reinterpret_cast<const float4*>(&As[k][ty * 8 + 4]);
            const ulonglong2* bb =
                reinterpret_cast<const ulonglong2*>(&Bs[k][tx * 8]);
            ulonglong2 b01 = bb[0], b23 = bb[1];
            unsigned long long b2[4] = {b01.x, b01.y, b23.x, b23.y};
#pragma unroll
            for (int i = 0; i < 8; i++) {
                unsigned long long a2 = pack2(a[i], a[i]);
                fma2(acc[i][0], a2, b2[0]);
                fma2(acc[i][1], a2, b2[1]);
                fma2(acc[i][2], a2, b2[2]);
                fma2(acc[i][3], a2, b2[3]);
            }
        }
    }

#pragma unroll
    for (int i = 0; i < 8; i++) {
        int m = m0 + ty * 8 + i;
        float* crow = g_xp + (long)m * 256 + n0 + tx * 8;
#pragma unroll
        for (int j = 0; j < 4; j++) {
            float2 v;
            v.x = lo32(acc[i][j]) + __ldg(bias + n0 + tx * 8 + 2 * j);
            v.y = hi32(acc[i][j]) + __ldg(bias + n0 + tx * 8 + 2 * j + 1);
            *reinterpret_cast<float2*>(crow + 2 * j) = v;
        }
    }
}

// ---------------- LTC scan ----------------
// One 2-CTA cluster per batch. Thread (row=tid>>1, kh=tid&1) covers 64 local
// cols + 64 remote cols. Local partial computed BEFORE the mbar wait
// (overlaps the peer's DSMEM flight); only a 64-col dot sits after the wake.
// One shfl combine + one __syncthreads per step. hbuf quarters are stored at
// a 68-float stride so kh0/kh1 LDS.128 hit disjoint bank groups.
#define QS 68   // floats per 64-col quarter (4-word skew)

__global__ void __cluster_dims__(2, 1, 1) __launch_bounds__(256, 1) ltc_scan(
    const float* __restrict__ W_rec,
    const float* __restrict__ mask,
    const float* __restrict__ tau_raw,
    float* __restrict__ out, int col_off)
{
    __shared__ __align__(16) float hbuf[2][4 * QS];
    __shared__ __align__(8) unsigned long long mbar[2];

    unsigned rank;
    asm("mov.u32 %0, %%cluster_ctarank;" : "=r"(rank));
    const unsigned peer = rank ^ 1u;
    const int b = blockIdx.x >> 1;
    const int tid = threadIdx.x;
    const int ol = tid >> 1;                 // row 0..127
    const int kh = tid & 1;
    const int o = ((int)rank << 7) + ol;     // global output row

    const int qloc = ((int)rank << 1) + kh;  // local-col quarter index
    const int qrem = ((int)peer << 1) + kh;  // remote-col quarter index

    // ---- weights: 32 ull local cols + 32 ull remote cols ----
    unsigned long long wl[32], wm[32];
    {
        const float2* wr = reinterpret_cast<const float2*>(W_rec + (long)o * 256);
        const float2* mk = reinterpret_cast<const float2*>(mask + (long)o * 256);
        const int cl = qloc * 32;            // float2 base of local quarter
        const int cr = qrem * 32;
#pragma unroll
        for (int j = 0; j < 32; j++) {
            float2 a = __ldg(wr + cl + j), m = __ldg(mk + cl + j);
            wl[j] = pack2(a.x * m.x, a.y * m.y);
            float2 a2 = __ldg(wr + cr + j), m2 = __ldg(mk + cr + j);
            wm[j] = pack2(a2.x * m2.x, a2.y * m2.y);
        }
    }

    float inv_tau = 0.f, hreg = 0.f, xq = 0.f;
    const float* xpp = g_xp + ((long)b * T_) * H_ + o;
    float* outp = out + ((long)b * T_) * 512 + col_off + o;
    if (kh == 0) {
        float tr = __ldg(tau_raw + o);
        float tau = log1pf(expf(tr)) + 0.1f;   // softplus + 0.1
        inv_tau = 1.0f / tau;
        xq = __ldg(xpp);                       // xp for t=0
    }

    // zero both h buffers (incl. skew pad)
    for (int i = tid; i < 2 * 4 * QS; i += 256)
        reinterpret_cast<float*>(hbuf)[i] = 0.0f;

    const unsigned lmb0 = smem_u32(&mbar[0]);
    const unsigned lmb1 = smem_u32(&mbar[1]);
    if (tid == 0) {
        mbar_init(lmb0, 1);
        mbar_init(lmb1, 1);
        mbar_expect_tx(lmb1, 512);   // consumed at t=1
        mbar_expect_tx(lmb0, 512);   // consumed at t=2
    }
    asm volatile("barrier.cluster.arrive.aligned;" ::: "memory");
    asm volatile("barrier.cluster.wait.aligned;" ::: "memory");

    // peer-side st.async targets for this row's h (both buffers)
    unsigned dAddr[2], mAddr[2];
    if (kh == 0) {
        const int po = ((int)rank << 1) * QS + ol;   // p(o): quarter*(QS)+in-quarter
        // o's quarter = rank*2 + (ol>=64), in-quarter = ol&63
        const int pq = ((int)rank << 1) + (ol >> 6);
        const int pidx = pq * QS + (ol & 63);
        (void)po;
#pragma unroll
        for (int bf = 0; bf < 2; bf++) {
            dAddr[bf] = mapa_rank(smem_u32(&hbuf[bf][pidx]), peer);
            mAddr[bf] = mapa_rank(bf ? lmb1 : lmb0, peer);
        }
    }
    const int selfq = ((int)rank << 1) + (ol >> 6);
    const int selfidx = selfq * QS + (ol & 63);

    float hn = 0.0f;

    for (int t = 0; t < T_; ++t) {
        const int cur = t & 1;

        // publish previous step's h to the peer (h state for THIS step)
        if (kh == 0 && t > 0) {
            st_async_f32(dAddr[cur], hn, mAddr[cur]);
        }

        // local-col partial: data ready since last barrier; overlaps flight
        unsigned long long a0 = 0ull, a1 = 0ull, a2 = 0ull, a3 = 0ull;
        {
            const ulonglong2* hl =
                reinterpret_cast<const ulonglong2*>(&hbuf[cur][qloc * QS]);
#pragma unroll
            for (int j = 0; j < 16; j += 2) {
                ulonglong2 x0 = hl[j];
                ulonglong2 x1 = hl[j + 1];
                fma2(a0, wl[2 * j + 0], x0.x);
                fma2(a1, wl[2 * j + 1], x0.y);
                fma2(a2, wl[2 * j + 2], x1.x);
                fma2(a3, wl[2 * j + 3], x1.y);
            }
        }

        // prefetch next xp while waiting
        float xn = 0.0f;
        if (kh == 0 && t + 1 < T_) xn = __ldg(xpp + (long)(t + 1) * H_);

        if (t > 0) {
            unsigned parity = (unsigned)((t - 1) >> 1) & 1u;
            mbar_wait_parity(cur ? lmb1 : lmb0, parity);
            if (tid == 0 && t + 2 < T_) {
                mbar_expect_tx(cur ? lmb1 : lmb0, 512);   // re-arm for t+2
            }
        }

        // remote-col partial (only 16 LDS + 32 fma2 after the wake)
        {
            const ulonglong2* hr =
                reinterpret_cast<const ulonglong2*>(&hbuf[cur][qrem * QS]);
#pragma unroll
            for (int j = 0; j < 16; j += 2) {
                ulonglong2 x0 = hr[j];
                ulonglong2 x1 = hr[j + 1];
                fma2(a0, wm[2 * j + 0], x0.x);
                fma2(a1, wm[2 * j + 1], x0.y);
                fma2(a2, wm[2 * j + 2], x1.x);
                fma2(a3, wm[2 * j + 3], x1.y);
            }
        }

        float s = ((lo32(a0) + hi32(a0)) + (lo32(a1) + hi32(a1))) +
                  ((lo32(a2) + hi32(a2)) + (lo32(a3) + hi32(a3)));
        s += __shfl_xor_sync(0xffffffffu, s, 1);

        if (kh == 0) {
            float pre = s + xq;
            hn = fmaf(fast_tanh(pre) - hreg, inv_tau, hreg);
            hreg = hn;
            outp[(long)t * 512] = hn;
            hbuf[cur ^ 1][selfidx] = hn;     // local publish for next step
            xq = xn;
        }
        // orders: local publish -> next step's local reads; re-arm -> next
        // step's st.async sends
        __syncthreads();
    }

    if (tid == 0) { mbar_inval(lmb0); mbar_inval(lmb1); }
}

// ---------------- launcher ----------------

extern "C" void kernel_launch(void* const* d_in, const int* in_sizes, int n_in,
                              void* d_out, int out_size) {
    const int*   tokens = (const int*)  d_in[0];
    const float* emb    = (const float*)d_in[1];
    const float* W_in0  = (const float*)d_in[2];
    const float* W_rec0 = (const float*)d_in[3];
    const float* b0     = (const float*)d_in[4];
    const float* tau0   = (const float*)d_in[5];
    const float* mask0  = (const float*)d_in[6];
    const float* W_in1  = (const float*)d_in[7];
    const float* W_rec1 = (const float*)d_in[8];
    const float* b1     = (const float*)d_in[9];
    const float* tau1   = (const float*)d_in[10];
    const float* mask1  = (const float*)d_in[11];
    float* out = (float*)d_out;

    dim3 gemm_grid(M_ / 128, 2);

    // level 0
    xp_gemm<<<gemm_grid, 256>>>(emb, E_, tokens, W_in0, b0);
    ltc_scan<<<2 * B_, 256>>>(W_rec0, mask0, tau0, out, 0);

    // level 1
    xp_gemm<<<gemm_grid, 256>>>(out, 512, nullptr, W_in1, b1);
    ltc_scan<<<2 * B_, 256>>>(W_rec1, mask1, tau1, out, 256);
}